// round 1
// baseline (speedup 1.0000x reference)
#include <cuda_runtime.h>
#include <math.h>

#define NB   512      // graphs
#define NPG  256      // nodes per graph
#define EPG  4096     // edges per graph
#define FIN  128
#define HDIM 64
#define TCLS 18
#define KTOP 16
#define FSTR 260      // padded feature stride (257 -> 260 for float4 alignment)
#define HS   65       // smem row stride (bank-conflict-free)

// global scratch for hidden features: [N][260], layers 0..3 at cols 0..255, layer4 at col 256
__device__ float g_feat[(size_t)NB * NPG * FSTR];

static __device__ __forceinline__ unsigned long long pk2(float lo, float hi) {
    unsigned long long r;
    asm("mov.b64 %0, {%1, %2};" : "=l"(r) : "f"(lo), "f"(hi));
    return r;
}
static __device__ __forceinline__ void upk2(unsigned long long v, float &lo, float &hi) {
    asm("mov.b64 {%0, %1}, %2;" : "=f"(lo), "=f"(hi) : "l"(v));
}
static __device__ __forceinline__ void fma2(unsigned long long &acc, unsigned long long a, unsigned long long b) {
    asm("fma.rn.f32x2 %0, %1, %2, %0;" : "+l"(acc) : "l"(a), "l"(b));
}

// dynamic smem layout (bytes):
//   hbuf:  NPG*HS floats            (66560)
//   lbuf:  NPG*HS floats            (66560)
//   wbuf:  64*64 floats             (16384)
//   invd:  NPG floats               (1024)
//   roff:  (NPG+1) ints             (1028)
//   cnt:   NPG ints                 (1024)
//   esrc:  EPG uchar                (4096)
//   s8:    EPG uchar                (4096)
//   d8:    EPG uchar                (4096)
#define GCN_SMEM_BYTES ((2*NPG*HS + HDIM*HDIM + NPG) * 4 + (NPG + 1 + NPG) * 4 + 3 * EPG)

__global__ void __launch_bounds__(256, 1) gcn_kernel(
    const float* __restrict__ x, const int* __restrict__ ei,
    const float* __restrict__ w0, const float* __restrict__ b0,
    const float* __restrict__ w1, const float* __restrict__ b1,
    const float* __restrict__ w2, const float* __restrict__ b2,
    const float* __restrict__ w3, const float* __restrict__ b3,
    const float* __restrict__ w4, const float* __restrict__ b4)
{
    extern __shared__ float sm[];
    float* hbuf = sm;
    float* lbuf = sm + NPG * HS;
    float* wbuf = sm + 2 * NPG * HS;
    float* invd = wbuf + HDIM * HDIM;
    int*   roff = (int*)(invd + NPG);
    int*   cnt  = roff + NPG + 1;
    unsigned char* esrc = (unsigned char*)(cnt + NPG);
    unsigned char* s8   = esrc + EPG;
    unsigned char* d8   = s8 + EPG;

    const int g = blockIdx.x, tid = threadIdx.x;
    const int eb = g * EPG;

    // ---- load edges (local ids: graph base is 256-aligned so low 8 bits = local idx) ----
    for (int e = tid; e < EPG; e += 256) {
        s8[e] = (unsigned char)(ei[eb + e] & 255);
        d8[e] = (unsigned char)(ei[(size_t)NB * EPG + eb + e] & 255);
    }
    cnt[tid] = 1;  // self loop
    __syncthreads();
    for (int e = tid; e < EPG; e += 256) atomicAdd(&cnt[s8[e]], 1);
    __syncthreads();
    invd[tid] = 1.0f / (float)cnt[tid];
    __syncthreads();
    // ---- CSR by dst ----
    cnt[tid] = 0;
    __syncthreads();
    for (int e = tid; e < EPG; e += 256) atomicAdd(&cnt[d8[e]], 1);
    __syncthreads();
    if (tid == 0) {
        int s = 0;
        for (int v = 0; v < NPG; v++) { roff[v] = s; s += cnt[v]; }
        roff[NPG] = s;
    }
    __syncthreads();
    cnt[tid] = roff[tid];  // cursor
    __syncthreads();
    for (int e = tid; e < EPG; e += 256) {
        int p = atomicAdd(&cnt[d8[e]], 1);
        esrc[p] = s8[e];
    }
    __syncthreads();

    const float* Wp[5] = {w0, w1, w2, w3, w4};
    const float* Bp[5] = {b0, b1, b2, b3, b4};

    unsigned long long acc[32];

    // ---- layers 0..3 (64 output channels) ----
    for (int L = 0; L < 4; L++) {
#pragma unroll
        for (int j = 0; j < 32; j++) acc[j] = 0ull;
        const int nch = (L == 0) ? 2 : 1;
        for (int ch = 0; ch < nch; ch++) {
            if (L == 0) {
                // stage x k-chunk into hbuf (coalesced)
                for (int i = tid; i < NPG * 64; i += 256) {
                    int n = i >> 6, k = i & 63;
                    hbuf[n * HS + k] = x[(size_t)(g * NPG + n) * FIN + ch * 64 + k];
                }
                for (int i = tid; i < 4096; i += 256) {
                    int o = i & 63, k = i >> 6;
                    wbuf[k * 64 + o] = w0[o * FIN + ch * 64 + k];
                }
            } else {
                const float* WL = Wp[L];
                for (int i = tid; i < 4096; i += 256) {
                    int o = i & 63, k = i >> 6;
                    wbuf[k * 64 + o] = WL[o * 64 + k];
                }
            }
            __syncthreads();
            // GEMM: thread = node row; 64 outputs in regs as 32 f32x2 pairs
            const float* hr = hbuf + tid * HS;
#pragma unroll 4
            for (int k = 0; k < 64; k++) {
                float hv = hr[k];
                unsigned long long hh = pk2(hv, hv);
                const ulonglong2* wp = (const ulonglong2*)(wbuf + k * 64);
#pragma unroll
                for (int j = 0; j < 16; j++) {
                    ulonglong2 w2 = wp[j];
                    fma2(acc[2 * j],     hh, w2.x);
                    fma2(acc[2 * j + 1], hh, w2.y);
                }
            }
            __syncthreads();
        }
        // ---- bias + write lin to lbuf, init accumulator (self loop) in hbuf ----
        {
            const float* bb = Bp[L];
            float* lr = lbuf + tid * HS;
            float* hw = hbuf + tid * HS;
#pragma unroll
            for (int j = 0; j < 32; j++) {
                float a, b;
                upk2(acc[j], a, b);
                float v0 = a + bb[2 * j], v1 = b + bb[2 * j + 1];
                lr[2 * j] = v0; lr[2 * j + 1] = v1;
                hw[2 * j] = v0; hw[2 * j + 1] = v1;
            }
        }
        __syncthreads();
        // ---- atomic-free aggregation via dst-CSR: owner = (node mod 4, channel) ----
        {
            int c = tid & 63, grp = tid >> 6;
            for (int v = grp; v < NPG; v += 4) {
                float a = hbuf[v * HS + c];       // self-loop term (= lin[v][c])
                int e1 = roff[v + 1];
                for (int e = roff[v]; e < e1; e++)
                    a += lbuf[(int)esrc[e] * HS + c];
                hbuf[v * HS + c] = tanhf(a * invd[v]);
            }
        }
        __syncthreads();
        // ---- store hidden layer to global scratch ----
        {
            float4* dp = (float4*)(&g_feat[(size_t)(g * NPG + tid) * FSTR + L * 64]);
            const float* hr = hbuf + tid * HS;
#pragma unroll
            for (int q = 0; q < 16; q++)
                dp[q] = make_float4(hr[4 * q], hr[4 * q + 1], hr[4 * q + 2], hr[4 * q + 3]);
        }
    }

    // ---- layer 4 (1 output channel = sort score) ----
    {
        if (tid < 64) wbuf[tid] = w4[tid];
        __syncthreads();
        float s = b4[0];
        const float* hr = hbuf + tid * HS;
#pragma unroll
        for (int k = 0; k < 64; k++) s += hr[k] * wbuf[k];
        lbuf[tid] = s;
        __syncthreads();
        float a = s;  // self loop
        int e1 = roff[tid + 1];
        for (int e = roff[tid]; e < e1; e++) a += lbuf[(int)esrc[e]];
        a = tanhf(a * invd[tid]);
        g_feat[(size_t)(g * NPG + tid) * FSTR + 256] = a;
    }
}

// ---- per-graph head: top-16 stable selection + conv1/pool/conv2/dense/dense/logsoftmax ----
__global__ void __launch_bounds__(256) head_kernel(
    const float* __restrict__ c1w, const float* __restrict__ c1b,
    const float* __restrict__ c2w, const float* __restrict__ c2b,
    const float* __restrict__ d1w, const float* __restrict__ d1b,
    const float* __restrict__ d2w, const float* __restrict__ d2b,
    float* __restrict__ out)
{
    __shared__ float sc[NPG];
    __shared__ float rv[NPG];
    __shared__ int   ri[NPG];
    __shared__ int   ord[KTOP];
    __shared__ float tk[KTOP * FSTR];
    __shared__ float c1ws[16 * 257];
    __shared__ float c1s[256];   // [o*16 + l]
    __shared__ float p1s[128];   // [o*8 + j]
    __shared__ float flats[128]; // [oc*4 + t]
    __shared__ float lasts[32];
    __shared__ float outs[TCLS];
    __shared__ float lse_s;

    const int g = blockIdx.x, tid = threadIdx.x;

    sc[tid] = g_feat[(size_t)(g * NPG + tid) * FSTR + 256];
    for (int i = tid; i < 16 * 257; i += 256) c1ws[i] = c1w[i];
    __syncthreads();

    // stable top-16 (value desc, index asc on ties) — matches stable argsort(-x)
    for (int r = 0; r < KTOP; r++) {
        rv[tid] = sc[tid]; ri[tid] = tid;
        __syncthreads();
        for (int s = 128; s > 0; s >>= 1) {
            if (tid < s) {
                float v2 = rv[tid + s]; int i2 = ri[tid + s];
                if (v2 > rv[tid] || (v2 == rv[tid] && i2 < ri[tid])) { rv[tid] = v2; ri[tid] = i2; }
            }
            __syncthreads();
        }
        if (tid == 0) ord[r] = ri[0];
        __syncthreads();
        if (tid == ord[r]) sc[tid] = -3.4e38f;
        __syncthreads();
    }

    // gather top-k features [16][257]
    for (int i = tid; i < KTOP * 257; i += 256) {
        int l = i / 257, d = i - l * 257;
        tk[l * FSTR + d] = g_feat[(size_t)(g * NPG + ord[l]) * FSTR + d];
    }
    __syncthreads();

    // conv1: per-slot matmul, 16 out ch x 16 slots
    {
        int o = tid & 15, l = tid >> 4;
        float s = c1b[o];
        const float* tr = &tk[l * FSTR];
        const float* wr = &c1ws[o * 257];
        for (int d = 0; d < 257; d++) s += tr[d] * wr[d];
        c1s[o * 16 + l] = fmaxf(s, 0.0f);
    }
    __syncthreads();
    // maxpool(2,2) along slots
    if (tid < 128) {
        int o = tid >> 3, j = tid & 7;
        p1s[tid] = fmaxf(c1s[o * 16 + 2 * j], c1s[o * 16 + 2 * j + 1]);
    }
    __syncthreads();
    // conv2: 16->32 ch, kernel 5, valid -> 4 positions
    if (tid < 128) {
        int oc = tid >> 2, t = tid & 3;
        float s = c2b[oc];
        for (int ic = 0; ic < 16; ic++) {
            const float* pr = &p1s[ic * 8 + t];
            const float* wr = &c2w[oc * 80 + ic * 5];
#pragma unroll
            for (int k = 0; k < 5; k++) s += pr[k] * wr[k];
        }
        flats[tid] = fmaxf(s, 0.0f);  // flat[oc*4+t] == tid
    }
    __syncthreads();
    // dense1: 128 -> 32, relu
    if (tid < 32) {
        float s = d1b[tid];
        const float* wr = &d1w[tid * 128];
        for (int i = 0; i < 128; i++) s += flats[i] * wr[i];
        float l = fmaxf(s, 0.0f);
        lasts[tid] = l;
        out[2 * NB * TCLS + g * 32 + tid] = l;   // third output: last
    }
    __syncthreads();
    // dense2: 32 -> 18
    if (tid < TCLS) {
        float s = d2b[tid];
        const float* wr = &d2w[tid * 32];
        for (int j = 0; j < 32; j++) s += lasts[j] * wr[j];
        outs[tid] = s;
        out[NB * TCLS + g * TCLS + tid] = s;     // second output: logits
    }
    __syncthreads();
    if (tid == 0) {
        float m = outs[0];
        for (int t = 1; t < TCLS; t++) m = fmaxf(m, outs[t]);
        float s = 0.0f;
        for (int t = 0; t < TCLS; t++) s += expf(outs[t] - m);
        lse_s = m + logf(s);
    }
    __syncthreads();
    if (tid < TCLS) out[g * TCLS + tid] = outs[tid] - lse_s;  // first output: log_softmax
}

extern "C" void kernel_launch(void* const* d_in, const int* in_sizes, int n_in,
                              void* d_out, int out_size)
{
    const float* x  = (const float*)d_in[0];
    const int*   ei = (const int*)  d_in[1];
    // input 2 = batch (unused), input 3 = num_graphs (scalar) if present
    const int wb = (n_in >= 22) ? 4 : 3;
    const float* W[5]; const float* Bv[5];
    for (int i = 0; i < 5; i++) {
        W[i]  = (const float*)d_in[wb + 2 * i];
        Bv[i] = (const float*)d_in[wb + 2 * i + 1];
    }
    const float* c1w = (const float*)d_in[wb + 10];
    const float* c1b = (const float*)d_in[wb + 11];
    const float* c2w = (const float*)d_in[wb + 12];
    const float* c2b = (const float*)d_in[wb + 13];
    const float* d1w = (const float*)d_in[wb + 14];
    const float* d1b = (const float*)d_in[wb + 15];
    const float* d2w = (const float*)d_in[wb + 16];
    const float* d2b = (const float*)d_in[wb + 17];

    cudaFuncSetAttribute(gcn_kernel, cudaFuncAttributeMaxDynamicSharedMemorySize, GCN_SMEM_BYTES);
    gcn_kernel<<<NB, 256, GCN_SMEM_BYTES>>>(x, ei,
        W[0], Bv[0], W[1], Bv[1], W[2], Bv[2], W[3], Bv[3], W[4], Bv[4]);
    head_kernel<<<NB, 256>>>(c1w, c1b, c2w, c2b, d1w, d1b, d2w, d2b, (float*)d_out);
}

// round 2
// speedup vs baseline: 1.1131x; 1.1131x over previous
#include <cuda_runtime.h>
#include <math.h>

#define NB   512      // graphs
#define NPG  256      // nodes per graph
#define EPG  4096     // edges per graph
#define FIN  128
#define HDIM 64
#define TCLS 18
#define KTOP 16
#define FSTR 256      // g_feat row: layers 0..3 only (score kept in smem)
#define HS   65       // smem row stride (bank-conflict-free)
#define NT   512      // threads per block

// global scratch for hidden features: [N][256] (layers 0..3)
__device__ float g_feat[(size_t)NB * NPG * FSTR];

static __device__ __forceinline__ unsigned long long pk2(float lo, float hi) {
    unsigned long long r;
    asm("mov.b64 %0, {%1, %2};" : "=l"(r) : "f"(lo), "f"(hi));
    return r;
}
static __device__ __forceinline__ void upk2(unsigned long long v, float &lo, float &hi) {
    asm("mov.b64 {%0, %1}, %2;" : "=f"(lo), "=f"(hi) : "l"(v));
}
static __device__ __forceinline__ void fma2(unsigned long long &acc, unsigned long long a, unsigned long long b) {
    asm("fma.rn.f32x2 %0, %1, %2, %0;" : "+l"(acc) : "l"(a), "l"(b));
}

// dynamic smem (bytes):
//   hbuf NPG*HS f | lbuf NPG*HS f | wbuf 4096 f | invd 256 f |
//   roff 257 i | cnt 256 i | eoff EPG u16 | s8 EPG u8 | d8 EPG u8
#define SMEM_BYTES ((2*NPG*HS + 4096 + NPG) * 4 + (NPG + 1 + NPG) * 4 + EPG * 2 + 2 * EPG)

__global__ void __launch_bounds__(NT, 1) dgcnn_kernel(
    const float* __restrict__ x, const int* __restrict__ ei,
    const float* __restrict__ w0, const float* __restrict__ b0,
    const float* __restrict__ w1, const float* __restrict__ b1,
    const float* __restrict__ w2, const float* __restrict__ b2,
    const float* __restrict__ w3, const float* __restrict__ b3,
    const float* __restrict__ w4, const float* __restrict__ b4,
    const float* __restrict__ c1w, const float* __restrict__ c1b,
    const float* __restrict__ c2w, const float* __restrict__ c2b,
    const float* __restrict__ d1w, const float* __restrict__ d1b,
    const float* __restrict__ d2w, const float* __restrict__ d2b,
    float* __restrict__ out)
{
    extern __shared__ float sm[];
    float* hbuf = sm;
    float* lbuf = sm + NPG * HS;
    float* wbuf = sm + 2 * NPG * HS;
    float* invd = wbuf + 4096;
    int*   roff = (int*)(invd + NPG);
    int*   cnt  = roff + NPG + 1;
    unsigned short* eoff = (unsigned short*)(cnt + NPG);
    unsigned char*  s8   = (unsigned char*)(eoff + EPG);
    unsigned char*  d8   = s8 + EPG;

    __shared__ float sc[NPG];    // final scores (preserved)
    __shared__ float sc2[NPG];   // destroyed during selection
    __shared__ float rv[NPG];
    __shared__ int   ri[NPG];
    __shared__ int   ord[KTOP];
    __shared__ float c1s[256];
    __shared__ float p1s[128];
    __shared__ float flats[128];
    __shared__ float lasts[32];
    __shared__ float outs[TCLS];
    __shared__ float lse_s;

    const int g = blockIdx.x, tid = threadIdx.x;
    const int eb = g * EPG;

    // ---- load edges (graph base 256-aligned: low 8 bits = local id) ----
    for (int e = tid; e < EPG; e += NT) {
        s8[e] = (unsigned char)(ei[eb + e] & 255);
        d8[e] = (unsigned char)(ei[(size_t)NB * EPG + eb + e] & 255);
    }
    int* dcn = (int*)lbuf;  // dst histogram / scan scratch (lbuf free here)
    if (tid < NPG) { cnt[tid] = 1; dcn[tid] = 0; }
    __syncthreads();
    for (int e = tid; e < EPG; e += NT) {
        atomicAdd(&cnt[s8[e]], 1);   // src degree (+self) -> norm
        atomicAdd(&dcn[d8[e]], 1);   // dst counts -> CSR
    }
    __syncthreads();
    if (tid < NPG) invd[tid] = 1.0f / (float)cnt[tid];
    // parallel inclusive scan over dcn (Hillis-Steele, in place)
    for (int s = 1; s < NPG; s <<= 1) {
        int t = 0;
        if (tid < NPG) { t = dcn[tid]; if (tid >= s) t += dcn[tid - s]; }
        __syncthreads();
        if (tid < NPG) dcn[tid] = t;
        __syncthreads();
    }
    if (tid < NPG) roff[tid + 1] = dcn[tid];
    if (tid == 0)  roff[0] = 0;
    __syncthreads();
    if (tid < NPG) cnt[tid] = roff[tid];  // cursors
    __syncthreads();
    for (int e = tid; e < EPG; e += NT) {
        int p = atomicAdd(&cnt[d8[e]], 1);
        eoff[p] = (unsigned short)((int)s8[e] * HS);  // premultiplied src offset
    }
    __syncthreads();

    const float* Wp[4] = {w0, w1, w2, w3};
    const float* Bp[4] = {b0, b1, b2, b3};
    const int node = tid & 255, half = tid >> 8;

    // ---- layers 0..3 ----
    for (int L = 0; L < 4; L++) {
        unsigned long long acc[16];
#pragma unroll
        for (int j = 0; j < 16; j++) acc[j] = 0ull;
        const int nch = (L == 0) ? 2 : 1;
        for (int ch = 0; ch < nch; ch++) {
            if (L == 0) {
                for (int i = tid; i < NPG * 64; i += NT) {
                    int n = i >> 6, k = i & 63;
                    hbuf[n * HS + k] = x[(size_t)(g * NPG + n) * FIN + ch * 64 + k];
                }
                for (int i = tid; i < 4096; i += NT) {
                    int o = i & 63, k = i >> 6;
                    wbuf[k * 64 + o] = w0[o * FIN + ch * 64 + k];
                }
            } else {
                const float* WL = Wp[L];
                for (int i = tid; i < 4096; i += NT) {
                    int o = i & 63, k = i >> 6;
                    wbuf[k * 64 + o] = WL[o * 64 + k];
                }
            }
            __syncthreads();
            // GEMM: (node, half) -> 32 outputs as 16 f32x2 accumulators
            const float* hr = hbuf + node * HS;
#pragma unroll 2
            for (int k = 0; k < 64; k++) {
                float hv = hr[k];
                unsigned long long hh = pk2(hv, hv);
                const ulonglong2* wp = (const ulonglong2*)(wbuf + k * 64 + half * 32);
#pragma unroll
                for (int j = 0; j < 8; j++) {
                    ulonglong2 q = wp[j];
                    fma2(acc[2 * j],     hh, q.x);
                    fma2(acc[2 * j + 1], hh, q.y);
                }
            }
            __syncthreads();
        }
        // bias + write lin to lbuf
        {
            const float* bb = Bp[L];
            float* lr = lbuf + node * HS + half * 32;
#pragma unroll
            for (int j = 0; j < 16; j++) {
                float a, b;
                upk2(acc[j], a, b);
                lr[2 * j]     = a + bb[half * 32 + 2 * j];
                lr[2 * j + 1] = b + bb[half * 32 + 2 * j + 1];
            }
        }
        __syncthreads();
        // aggregation: warp-uniform edge list, 4-way MLP unroll
        {
            int c = tid & 63, grp = tid >> 6;
            for (int v = grp; v < NPG; v += 8) {
                const float iv = invd[v];
                float a = lbuf[v * HS + c];  // self loop
                int e = roff[v], e1 = roff[v + 1];
                float a0 = 0.f, a1 = 0.f, a2 = 0.f, a3 = 0.f;
                for (; e + 4 <= e1; e += 4) {
                    a0 += lbuf[eoff[e]     + c];
                    a1 += lbuf[eoff[e + 1] + c];
                    a2 += lbuf[eoff[e + 2] + c];
                    a3 += lbuf[eoff[e + 3] + c];
                }
                for (; e < e1; e++) a += lbuf[eoff[e] + c];
                a += (a0 + a1) + (a2 + a3);
                hbuf[v * HS + c] = tanhf(a * iv);
            }
        }
        __syncthreads();
        // store hidden layer to global scratch (each thread: 32 contiguous floats)
        {
            int n = tid >> 1, part = tid & 1;
            float4* dp = (float4*)(&g_feat[(size_t)(g * NPG + n) * FSTR + L * 64 + part * 32]);
            const float* hr2 = hbuf + n * HS + part * 32;
#pragma unroll
            for (int q = 0; q < 8; q++)
                dp[q] = make_float4(hr2[4 * q], hr2[4 * q + 1], hr2[4 * q + 2], hr2[4 * q + 3]);
        }
    }

    // ---- layer 4: sort scores ----
    if (tid < 64) wbuf[tid] = w4[tid];
    __syncthreads();
    if (tid < NPG) {
        float s = b4[0];
        const float* hr = hbuf + tid * HS;
#pragma unroll
        for (int k = 0; k < 64; k++) s += hr[k] * wbuf[k];
        lbuf[tid * HS] = s;
    }
    __syncthreads();
    if (tid < NPG) {
        float a = lbuf[tid * HS];  // self
        int e = roff[tid], e1 = roff[tid + 1];
        float a0 = 0.f, a1 = 0.f, a2 = 0.f, a3 = 0.f;
        for (; e + 4 <= e1; e += 4) {
            a0 += lbuf[eoff[e]];     a1 += lbuf[eoff[e + 1]];
            a2 += lbuf[eoff[e + 2]]; a3 += lbuf[eoff[e + 3]];
        }
        for (; e < e1; e++) a += lbuf[eoff[e]];
        a += (a0 + a1) + (a2 + a3);
        float t = tanhf(a * invd[tid]);
        sc[tid] = t; sc2[tid] = t;
    }
    __syncthreads();

    // ---- stable top-16 (value desc, index asc on ties) ----
    for (int r = 0; r < KTOP; r++) {
        if (tid < NPG) { rv[tid] = sc2[tid]; ri[tid] = tid; }
        __syncthreads();
        for (int s = 128; s > 0; s >>= 1) {
            if (tid < s) {
                float v2 = rv[tid + s]; int i2 = ri[tid + s];
                if (v2 > rv[tid] || (v2 == rv[tid] && i2 < ri[tid])) { rv[tid] = v2; ri[tid] = i2; }
            }
            __syncthreads();
        }
        if (tid == 0) { ord[r] = ri[0]; sc2[ri[0]] = -3.4e38f; }
        __syncthreads();
    }

    // ---- gather top-k features + conv1 weights (reuse lbuf/hbuf) ----
    float* tk   = lbuf;   // [16][260]
    float* c1ws = hbuf;   // [16*257]
    for (int i = tid; i < 16 * 257; i += NT) c1ws[i] = c1w[i];
    for (int i = tid; i < KTOP * 257; i += NT) {
        int l = i / 257, d = i - l * 257;
        tk[l * 260 + d] = (d < 256) ? g_feat[(size_t)(g * NPG + ord[l]) * FSTR + d] : sc[ord[l]];
    }
    __syncthreads();

    // conv1: 16 out ch x 16 slots, 257-dot (4-way unrolled)
    if (tid < 256) {
        int o = tid & 15, l = tid >> 4;
        const float* tr = tk + l * 260;
        const float* wr = c1ws + o * 257;
        float s0 = 0.f, s1 = 0.f, s2 = 0.f, s3 = 0.f;
        for (int d = 0; d < 256; d += 4) {
            s0 += tr[d] * wr[d];         s1 += tr[d + 1] * wr[d + 1];
            s2 += tr[d + 2] * wr[d + 2]; s3 += tr[d + 3] * wr[d + 3];
        }
        float s = c1b[o] + tr[256] * wr[256] + (s0 + s1) + (s2 + s3);
        c1s[o * 16 + l] = fmaxf(s, 0.0f);
    }
    __syncthreads();
    if (tid < 128) {
        int o = tid >> 3, j = tid & 7;
        p1s[tid] = fmaxf(c1s[o * 16 + 2 * j], c1s[o * 16 + 2 * j + 1]);
    }
    __syncthreads();
    if (tid < 128) {
        int oc = tid >> 2, t = tid & 3;
        float s = c2b[oc];
        for (int ic = 0; ic < 16; ic++) {
            const float* pr = &p1s[ic * 8 + t];
            const float* wr = &c2w[oc * 80 + ic * 5];
#pragma unroll
            for (int k = 0; k < 5; k++) s += pr[k] * wr[k];
        }
        flats[tid] = fmaxf(s, 0.0f);
    }
    __syncthreads();
    if (tid < 32) {
        float s = d1b[tid];
        const float* wr = &d1w[tid * 128];
#pragma unroll 4
        for (int i = 0; i < 128; i++) s += flats[i] * wr[i];
        float l = fmaxf(s, 0.0f);
        lasts[tid] = l;
        out[2 * NB * TCLS + g * 32 + tid] = l;
    }
    __syncthreads();
    if (tid < TCLS) {
        float s = d2b[tid];
        const float* wr = &d2w[tid * 32];
#pragma unroll
        for (int j = 0; j < 32; j++) s += lasts[j] * wr[j];
        outs[tid] = s;
        out[NB * TCLS + g * TCLS + tid] = s;
    }
    __syncthreads();
    if (tid == 0) {
        float m = outs[0];
        for (int t = 1; t < TCLS; t++) m = fmaxf(m, outs[t]);
        float s = 0.0f;
        for (int t = 0; t < TCLS; t++) s += expf(outs[t] - m);
        lse_s = m + logf(s);
    }
    __syncthreads();
    if (tid < TCLS) out[g * TCLS + tid] = outs[tid] - lse_s;
}

extern "C" void kernel_launch(void* const* d_in, const int* in_sizes, int n_in,
                              void* d_out, int out_size)
{
    const float* x  = (const float*)d_in[0];
    const int*   ei = (const int*)  d_in[1];
    const int wb = (n_in >= 22) ? 4 : 3;
    const float* W[5]; const float* Bv[5];
    for (int i = 0; i < 5; i++) {
        W[i]  = (const float*)d_in[wb + 2 * i];
        Bv[i] = (const float*)d_in[wb + 2 * i + 1];
    }
    const float* c1w = (const float*)d_in[wb + 10];
    const float* c1b = (const float*)d_in[wb + 11];
    const float* c2w = (const float*)d_in[wb + 12];
    const float* c2b = (const float*)d_in[wb + 13];
    const float* d1w = (const float*)d_in[wb + 14];
    const float* d1b = (const float*)d_in[wb + 15];
    const float* d2w = (const float*)d_in[wb + 16];
    const float* d2b = (const float*)d_in[wb + 17];

    cudaFuncSetAttribute(dgcnn_kernel, cudaFuncAttributeMaxDynamicSharedMemorySize, SMEM_BYTES);
    dgcnn_kernel<<<NB, NT, SMEM_BYTES>>>(x, ei,
        W[0], Bv[0], W[1], Bv[1], W[2], Bv[2], W[3], Bv[3], W[4], Bv[4],
        c1w, c1b, c2w, c2b, d1w, d1b, d2w, d2b, (float*)d_out);
}

// round 3
// speedup vs baseline: 1.4642x; 1.3154x over previous
#include <cuda_runtime.h>
#include <math.h>

#define NB   512
#define NPG  256
#define EPG  4096
#define FIN  128
#define TCLS 18
#define KTOP 16
#define FSTR 256      // g_feat row: layers 0..3
#define VS   257      // transposed smem row stride: [64][257] (col 256 = zero pad)
#define HTW  16452    // 64*257 rounded up to mult of 4
#define NT   512

__device__ float g_feat[(size_t)NB * NPG * FSTR];

static __device__ __forceinline__ unsigned long long pk2(float lo, float hi) {
    unsigned long long r;
    asm("mov.b64 %0, {%1, %2};" : "=l"(r) : "f"(lo), "f"(hi));
    return r;
}
static __device__ __forceinline__ void upk2(unsigned long long v, float &lo, float &hi) {
    asm("mov.b64 {%0, %1}, %2;" : "=f"(lo), "=f"(hi) : "l"(v));
}
static __device__ __forceinline__ void fma2(unsigned long long &acc, unsigned long long a, unsigned long long b) {
    asm("fma.rn.f32x2 %0, %1, %2, %0;" : "+l"(acc) : "l"(a), "l"(b));
}

// dynamic smem: ht[HTW] | lt[HTW] | wbuf[4096] | invd[256] | roff[260]i | cnt[256]i | eoff[6144]u16 | s8[4096] | d8[4096]
#define SMEM_BYTES ((2*HTW + 4096 + 256) * 4 + (260 + 256) * 4 + 6144 * 2 + 2 * 4096)

__global__ void __launch_bounds__(NT, 1) dgcnn_kernel(
    const float* __restrict__ x, const int* __restrict__ ei,
    const float* __restrict__ w0, const float* __restrict__ b0,
    const float* __restrict__ w1, const float* __restrict__ b1,
    const float* __restrict__ w2, const float* __restrict__ b2,
    const float* __restrict__ w3, const float* __restrict__ b3,
    const float* __restrict__ w4, const float* __restrict__ b4,
    const float* __restrict__ c1w, const float* __restrict__ c1b,
    const float* __restrict__ c2w, const float* __restrict__ c2b,
    const float* __restrict__ d1w, const float* __restrict__ d1b,
    const float* __restrict__ d2w, const float* __restrict__ d2b,
    float* __restrict__ out)
{
    extern __shared__ float sm[];
    float* ht   = sm;                       // transposed features [64][257]
    float* lt   = sm + HTW;                 // transposed lin      [64][257]
    float* wbuf = sm + 2 * HTW;             // 4096
    float* invd = wbuf + 4096;              // 256
    int*   roff = (int*)(invd + 256);       // 260
    int*   cnt  = roff + 260;               // 256
    unsigned short* eoff = (unsigned short*)(cnt + 256);   // 6144 (16B-aligned)
    unsigned char*  s8   = (unsigned char*)(eoff + 6144);
    unsigned char*  d8   = s8 + EPG;

    __shared__ float sc[NPG];
    __shared__ int   ord[KTOP];
    __shared__ float c1s[256];
    __shared__ float p1s[128];
    __shared__ float flats[128];
    __shared__ float lasts[32];
    __shared__ float outs[TCLS];
    __shared__ float lse_s;

    const int g = blockIdx.x, tid = threadIdx.x;
    const int eb = g * EPG;

    // ---- load edges (graph base 256-aligned: low 8 bits = local id) ----
    for (int e = tid; e < EPG; e += NT) {
        s8[e] = (unsigned char)(ei[eb + e] & 255);
        d8[e] = (unsigned char)(ei[(size_t)NB * EPG + eb + e] & 255);
    }
    int* dcn = (int*)ht;  // dst-count scratch (ht free now)
    if (tid < NPG) { cnt[tid] = 1; dcn[tid] = 0; }
    if (tid < 64)  lt[tid * VS + 256] = 0.0f;   // zero pad column (dummy gather target)
    __syncthreads();
    for (int e = tid; e < EPG; e += NT) {
        atomicAdd(&cnt[s8[e]], 1);   // src degree (+self) -> norm
        atomicAdd(&dcn[d8[e]], 1);   // dst counts -> CSR
    }
    __syncthreads();
    if (tid < NPG) invd[tid] = 1.0f / (float)cnt[tid];
    // padded counts (multiple of 8), Hillis-Steele inclusive scan in place
    if (tid < NPG) dcn[tid] = (dcn[tid] + 7) & ~7;
    __syncthreads();
    for (int s = 1; s < NPG; s <<= 1) {
        int t = 0;
        if (tid < NPG) { t = dcn[tid]; if (tid >= s) t += dcn[tid - s]; }
        __syncthreads();
        if (tid < NPG) dcn[tid] = t;
        __syncthreads();
    }
    if (tid < NPG) roff[tid + 1] = dcn[tid];
    if (tid == 0)  roff[0] = 0;
    __syncthreads();
    if (tid < NPG) cnt[tid] = roff[tid];  // cursors
    __syncthreads();
    for (int e = tid; e < EPG; e += NT) {
        int p = atomicAdd(&cnt[d8[e]], 1);
        eoff[p] = (unsigned short)s8[e];
    }
    __syncthreads();
    if (tid < NPG) {  // fill padding with dummy src 256 (points at zero column)
        int p = cnt[tid], p1 = roff[tid + 1];
        for (; p < p1; p++) eoff[p] = 256;
    }
    __syncthreads();

    const float* Wp[4] = {w0, w1, w2, w3};
    const float* Bp[4] = {b0, b1, b2, b3};
    const int oct = tid & 31;        // node octet base (node = oct + 32j)
    const int cg  = tid >> 5;        // channel group 0..15
    const int c4  = cg * 4;

    // ---- layers 0..3 ----
    for (int L = 0; L < 4; L++) {
        unsigned long long accL[8], accH[8];
#pragma unroll
        for (int j = 0; j < 8; j++) { accL[j] = 0ull; accH[j] = 0ull; }
        const int nch = (L == 0) ? 2 : 1;
        for (int ch = 0; ch < nch; ch++) {
            if (L == 0) {
                // stage x chunk transposed: ht[k][n]
                for (int i = tid; i < NPG * 16; i += NT) {
                    int n = i >> 4, kq = i & 15;
                    float4 v = *(const float4*)(x + (size_t)(g * NPG + n) * FIN + ch * 64 + kq * 4);
                    ht[(kq * 4 + 0) * VS + n] = v.x;
                    ht[(kq * 4 + 1) * VS + n] = v.y;
                    ht[(kq * 4 + 2) * VS + n] = v.z;
                    ht[(kq * 4 + 3) * VS + n] = v.w;
                }
                for (int i = tid; i < 4096; i += NT) {
                    int o = i & 63, k = i >> 6;
                    wbuf[k * 64 + o] = w0[o * FIN + ch * 64 + k];
                }
            } else {
                const float* WL = Wp[L];
                for (int i = tid; i < 4096; i += NT) {
                    int o = i & 63, k = i >> 6;
                    wbuf[k * 64 + o] = WL[o * 64 + k];
                }
            }
            __syncthreads();
            // GEMM: per k: 1 float4 weight (broadcast) + 8 independent h loads, 16 FFMA2
#pragma unroll 2
            for (int k = 0; k < 64; k++) {
                float4 w = *(const float4*)(wbuf + k * 64 + c4);
                unsigned long long wlo = pk2(w.x, w.y), whi = pk2(w.z, w.w);
                const float* hk = ht + k * VS + oct;
                float hv[8];
#pragma unroll
                for (int j = 0; j < 8; j++) hv[j] = hk[32 * j];
#pragma unroll
                for (int j = 0; j < 8; j++) {
                    unsigned long long hh = pk2(hv[j], hv[j]);
                    fma2(accL[j], hh, wlo);
                    fma2(accH[j], hh, whi);
                }
            }
            __syncthreads();
        }
        // bias + write lin transposed
        {
            const float* bb = Bp[L];
            float bv0 = bb[c4], bv1 = bb[c4 + 1], bv2 = bb[c4 + 2], bv3 = bb[c4 + 3];
#pragma unroll
            for (int j = 0; j < 8; j++) {
                int n = oct + 32 * j;
                float a, b, c, d;
                upk2(accL[j], a, b);
                upk2(accH[j], c, d);
                lt[(c4 + 0) * VS + n] = a + bv0;
                lt[(c4 + 1) * VS + n] = b + bv1;
                lt[(c4 + 2) * VS + n] = c + bv2;
                lt[(c4 + 3) * VS + n] = d + bv3;
            }
        }
        __syncthreads();
        // aggregation: 8-batched independent gathers
        {
            int c = tid & 63, grp = tid >> 6;
            const float* lc = lt + c * VS;
            for (int v = grp; v < NPG; v += 8) {
                float a = lc[v];  // self loop
                const float iv = invd[v];
                int e = roff[v], e1 = roff[v + 1];
                float a0 = 0.f, a1 = 0.f, a2 = 0.f, a3 = 0.f;
                for (; e < e1; e += 8) {
                    uint4 pk = *(const uint4*)(eoff + e);
                    a0 += lc[pk.x & 0xffff]; a1 += lc[pk.x >> 16];
                    a2 += lc[pk.y & 0xffff]; a3 += lc[pk.y >> 16];
                    a0 += lc[pk.z & 0xffff]; a1 += lc[pk.z >> 16];
                    a2 += lc[pk.w & 0xffff]; a3 += lc[pk.w >> 16];
                }
                a += (a0 + a1) + (a2 + a3);
                float r = tanhf(a * iv);
                ht[c * VS + v] = r;
                g_feat[(size_t)(g * NPG + v) * FSTR + L * 64 + c] = r;
            }
        }
        __syncthreads();
    }

    // ---- layer 4: sort scores ----
    if (tid < 64) wbuf[tid] = w4[tid];
    __syncthreads();
    if (tid < NPG) {
        float s = b4[0];
#pragma unroll 4
        for (int k = 0; k < 64; k++) s += ht[k * VS + tid] * wbuf[k];
        lt[tid] = s;  // row 0; lt[256] still zero
    }
    __syncthreads();
    if (tid < NPG) {
        float a = lt[tid];
        int e = roff[tid], e1 = roff[tid + 1];
        float a0 = 0.f, a1 = 0.f, a2 = 0.f, a3 = 0.f;
        for (; e < e1; e += 8) {
            uint4 pk = *(const uint4*)(eoff + e);
            a0 += lt[pk.x & 0xffff]; a1 += lt[pk.x >> 16];
            a2 += lt[pk.y & 0xffff]; a3 += lt[pk.y >> 16];
            a0 += lt[pk.z & 0xffff]; a1 += lt[pk.z >> 16];
            a2 += lt[pk.w & 0xffff]; a3 += lt[pk.w >> 16];
        }
        a += (a0 + a1) + (a2 + a3);
        sc[tid] = tanhf(a * invd[tid]);
    }
    __syncthreads();

    // ---- stable top-16: single warp, shfl butterfly (val desc, idx asc) ----
    if (tid < 32) {
        float v[8];
        const int base = tid * 8;
#pragma unroll
        for (int t = 0; t < 8; t++) v[t] = sc[base + t];
        for (int r = 0; r < KTOP; r++) {
            float bv = v[0]; int bi = base;
#pragma unroll
            for (int t = 1; t < 8; t++)
                if (v[t] > bv) { bv = v[t]; bi = base + t; }
#pragma unroll
            for (int off = 16; off > 0; off >>= 1) {
                float ov = __shfl_xor_sync(0xffffffffu, bv, off);
                int   oi = __shfl_xor_sync(0xffffffffu, bi, off);
                if (ov > bv || (ov == bv && oi < bi)) { bv = ov; bi = oi; }
            }
            if (tid == 0) ord[r] = bi;
            if ((bi >> 3) == tid) v[bi & 7] = -3.4e38f;
        }
    }
    __syncthreads();

    // ---- head (reuse lt as tk[16][260], ht as c1ws[16][260]) ----
    float* tk   = lt;
    float* c1ws = ht;
    for (int i = tid; i < 16 * 257; i += NT) {
        int o = i / 257, d = i - o * 257;
        c1ws[o * 260 + d] = c1w[i];
    }
    for (int i = tid; i < KTOP * 257; i += NT) {
        int l = i / 257, d = i - l * 257;
        tk[l * 260 + d] = (d < 256) ? g_feat[(size_t)(g * NPG + ord[l]) * FSTR + d] : sc[ord[l]];
    }
    __syncthreads();

    // conv1: 16 out ch x 16 slots, float4 dot over 256 + last elem
    if (tid < 256) {
        int o = tid & 15, l = tid >> 4;
        const float4* tr = (const float4*)(tk + l * 260);
        const float4* wr = (const float4*)(c1ws + o * 260);
        float s0 = 0.f, s1 = 0.f, s2 = 0.f, s3 = 0.f;
#pragma unroll 4
        for (int d = 0; d < 64; d++) {
            float4 a = tr[d], b = wr[d];
            s0 += a.x * b.x; s1 += a.y * b.y; s2 += a.z * b.z; s3 += a.w * b.w;
        }
        float s = c1b[o] + tk[l * 260 + 256] * c1ws[o * 260 + 256] + (s0 + s1) + (s2 + s3);
        c1s[o * 16 + l] = fmaxf(s, 0.0f);
    }
    __syncthreads();
    if (tid < 128) {
        int o = tid >> 3, j = tid & 7;
        p1s[tid] = fmaxf(c1s[o * 16 + 2 * j], c1s[o * 16 + 2 * j + 1]);
    }
    __syncthreads();
    if (tid < 128) {
        int oc = tid >> 2, t = tid & 3;
        float s = c2b[oc];
        for (int ic = 0; ic < 16; ic++) {
            const float* pr = &p1s[ic * 8 + t];
            const float* wr = &c2w[oc * 80 + ic * 5];
#pragma unroll
            for (int k = 0; k < 5; k++) s += pr[k] * wr[k];
        }
        flats[tid] = fmaxf(s, 0.0f);
    }
    __syncthreads();
    if (tid < 32) {
        float s = d1b[tid];
        const float4* wr = (const float4*)(d1w + tid * 128);
        const float4* fr = (const float4*)flats;
#pragma unroll 4
        for (int i = 0; i < 32; i++) {
            float4 a = fr[i], b = wr[i];
            s += a.x * b.x + a.y * b.y + a.z * b.z + a.w * b.w;
        }
        float l = fmaxf(s, 0.0f);
        lasts[tid] = l;
        out[2 * NB * TCLS + g * 32 + tid] = l;
    }
    __syncthreads();
    if (tid < TCLS) {
        float s = d2b[tid];
        const float* wr = &d2w[tid * 32];
#pragma unroll
        for (int j = 0; j < 32; j++) s += lasts[j] * wr[j];
        outs[tid] = s;
        out[NB * TCLS + g * TCLS + tid] = s;
    }
    __syncthreads();
    if (tid == 0) {
        float m = outs[0];
        for (int t = 1; t < TCLS; t++) m = fmaxf(m, outs[t]);
        float s = 0.0f;
        for (int t = 0; t < TCLS; t++) s += expf(outs[t] - m);
        lse_s = m + logf(s);
    }
    __syncthreads();
    if (tid < TCLS) out[g * TCLS + tid] = outs[tid] - lse_s;
}

extern "C" void kernel_launch(void* const* d_in, const int* in_sizes, int n_in,
                              void* d_out, int out_size)
{
    const float* x  = (const float*)d_in[0];
    const int*   ei = (const int*)  d_in[1];
    const int wb = (n_in >= 22) ? 4 : 3;
    const float* W[5]; const float* Bv[5];
    for (int i = 0; i < 5; i++) {
        W[i]  = (const float*)d_in[wb + 2 * i];
        Bv[i] = (const float*)d_in[wb + 2 * i + 1];
    }
    const float* c1w = (const float*)d_in[wb + 10];
    const float* c1b = (const float*)d_in[wb + 11];
    const float* c2w = (const float*)d_in[wb + 12];
    const float* c2b = (const float*)d_in[wb + 13];
    const float* d1w = (const float*)d_in[wb + 14];
    const float* d1b = (const float*)d_in[wb + 15];
    const float* d2w = (const float*)d_in[wb + 16];
    const float* d2b = (const float*)d_in[wb + 17];

    cudaFuncSetAttribute(dgcnn_kernel, cudaFuncAttributeMaxDynamicSharedMemorySize, SMEM_BYTES);
    dgcnn_kernel<<<NB, NT, SMEM_BYTES>>>(x, ei,
        W[0], Bv[0], W[1], Bv[1], W[2], Bv[2], W[3], Bv[3], W[4], Bv[4],
        c1w, c1b, c2w, c2b, d1w, d1b, d2w, d2b, (float*)d_out);
}

// round 5
// speedup vs baseline: 1.6324x; 1.1148x over previous
#include <cuda_runtime.h>
#include <math.h>

#define NB   512
#define NPG  256
#define EPG  4096
#define FIN  128
#define TCLS 18
#define KTOP 16
#define FSTR 256      // g_feat row: layers 0..3
#define VSH  258      // ht (channel-major) row stride, even for paired LDS.64
#define VSL  68       // lt (node-major) row stride, mult of 4 for STS.128
#define NT   1024

__device__ float g_feat[(size_t)NB * NPG * FSTR];

typedef unsigned long long ull;

static __device__ __forceinline__ ull pk2(float lo, float hi) {
    ull r; asm("mov.b64 %0, {%1, %2};" : "=l"(r) : "f"(lo), "f"(hi)); return r;
}
static __device__ __forceinline__ void upk2(ull v, float &lo, float &hi) {
    asm("mov.b64 {%0, %1}, %2;" : "=f"(lo), "=f"(hi) : "l"(v));
}
static __device__ __forceinline__ void fma2(ull &acc, ull a, ull b) {
    asm("fma.rn.f32x2 %0, %1, %2, %0;" : "+l"(acc) : "l"(a), "l"(b));
}
static __device__ __forceinline__ ull add2(ull a, ull b) {
    ull r; asm("add.rn.f32x2 %0, %1, %2;" : "=l"(r) : "l"(a), "l"(b)); return r;
}

// dynamic smem words:
//   ht:    64*VSH            = 16512
//   lt:    257*VSL           = 17476   (row 256 = zero pad for dummy gathers)
//   wbuf2: 4096 ull          =  8192 words (s8/d8 union this space during CSR build)
//   invd:  256
//   roff:  260 (int)
//   cnt:   256 (int)
//   eoff:  6144 u16          =  3072 words
#define W_HT   (64 * VSH)
#define W_LT   (257 * VSL)
#define W_WB   8192
#define SMEM_WORDS (W_HT + W_LT + W_WB + 256 + 260 + 256 + 3072)
#define SMEM_BYTES (SMEM_WORDS * 4)

__global__ void __launch_bounds__(NT, 1) dgcnn_kernel(
    const float* __restrict__ x, const int* __restrict__ ei,
    const float* __restrict__ w0, const float* __restrict__ b0,
    const float* __restrict__ w1, const float* __restrict__ b1,
    const float* __restrict__ w2, const float* __restrict__ b2,
    const float* __restrict__ w3, const float* __restrict__ b3,
    const float* __restrict__ w4, const float* __restrict__ b4,
    const float* __restrict__ c1w, const float* __restrict__ c1b,
    const float* __restrict__ c2w, const float* __restrict__ c2b,
    const float* __restrict__ d1w, const float* __restrict__ d1b,
    const float* __restrict__ d2w, const float* __restrict__ d2b,
    float* __restrict__ out)
{
    extern __shared__ float sm[];
    float* ht   = sm;                         // [64][VSH] channel-major features
    float* lt   = sm + W_HT;                  // [257][VSL] node-major lin
    ull*   wbuf2 = (ull*)(sm + W_HT + W_LT);  // [64][64] duplicated weights
    float* invd = sm + W_HT + W_LT + W_WB;
    int*   roff = (int*)(invd + 256);
    int*   cnt  = roff + 260;
    unsigned short* eoff = (unsigned short*)(cnt + 256);
    unsigned char*  s8   = (unsigned char*)wbuf2;       // union (CSR build phase only)
    unsigned char*  d8   = s8 + EPG;

    __shared__ float sc[NPG];
    __shared__ float w4s[64];
    __shared__ int   ord[KTOP];
    __shared__ float c1s[256];
    __shared__ float p1s[128];
    __shared__ float flats[128];
    __shared__ float lasts[32];
    __shared__ float outs[TCLS];
    __shared__ float lse_s;

    const int g = blockIdx.x, tid = threadIdx.x;
    const int eb = g * EPG;

    // ---- edges: graph base 256-aligned, low 8 bits = local id ----
    for (int e = tid; e < EPG; e += NT) {
        s8[e] = (unsigned char)(ei[eb + e] & 255);
        d8[e] = (unsigned char)(ei[(size_t)NB * EPG + eb + e] & 255);
    }
    int* dcn = (int*)ht;  // scratch
    if (tid < NPG) { cnt[tid] = 1; dcn[tid] = 0; }
    if (tid < VSL) lt[256 * VSL + tid] = 0.0f;   // zero pad row (dummy gather target)
    __syncthreads();
    for (int e = tid; e < EPG; e += NT) {
        atomicAdd(&cnt[s8[e]], 1);
        atomicAdd(&dcn[d8[e]], 1);
    }
    __syncthreads();
    if (tid < NPG) {
        invd[tid] = 1.0f / (float)cnt[tid];
        dcn[tid] = (dcn[tid] + 7) & ~7;          // pad to multiple of 8
    }
    __syncthreads();
    for (int s = 1; s < NPG; s <<= 1) {          // inclusive scan
        int t = 0;
        if (tid < NPG) { t = dcn[tid]; if (tid >= s) t += dcn[tid - s]; }
        __syncthreads();
        if (tid < NPG) dcn[tid] = t;
        __syncthreads();
    }
    if (tid < NPG) roff[tid + 1] = dcn[tid];
    if (tid == 0)  roff[0] = 0;
    __syncthreads();
    if (tid < NPG) cnt[tid] = roff[tid];
    __syncthreads();
    for (int e = tid; e < EPG; e += NT) {
        int p = atomicAdd(&cnt[d8[e]], 1);
        eoff[p] = (unsigned short)((int)s8[e] * VSL);   // premultiplied word offset
    }
    __syncthreads();
    if (tid < NPG) {
        int p = cnt[tid], p1 = roff[tid + 1];
        for (; p < p1; p++) eoff[p] = (unsigned short)(256 * VSL);  // dummy -> zero row
    }
    __syncthreads();

    const float* Wp[4] = {w0, w1, w2, w3};
    const float* Bp[4] = {b0, b1, b2, b3};
    const int lane  = tid & 31;
    const int cgp   = (tid >> 5) & 7;    // channel group (8 ch)
    const int ngp   = tid >> 8;          // node slice (0..3)
    const int c8    = cgp * 8;
    const int pbase = 2 * (lane + 32 * ngp);   // node pair (pbase, pbase+1)

    // ---- layers 0..3 ----
    for (int L = 0; L < 4; L++) {
        ull acc[8];
#pragma unroll
        for (int t = 0; t < 8; t++) acc[t] = 0ull;
        const int nch = (L == 0) ? 2 : 1;
        for (int ch = 0; ch < nch; ch++) {
            if (L == 0) {
                for (int i = tid; i < NPG * 16; i += NT) {
                    int n = i >> 4, kq = i & 15;
                    float4 v = *(const float4*)(x + (size_t)(g * NPG + n) * FIN + ch * 64 + kq * 4);
                    ht[(kq * 4 + 0) * VSH + n] = v.x;
                    ht[(kq * 4 + 1) * VSH + n] = v.y;
                    ht[(kq * 4 + 2) * VSH + n] = v.z;
                    ht[(kq * 4 + 3) * VSH + n] = v.w;
                }
            }
            // stage weights duplicated: wbuf2[k*64+o] = (w[o][k], w[o][k])
            {
                const float* WL = Wp[L];
                for (int i = tid; i < 4096; i += NT) {
                    int o = i & 63, k = i >> 6;
                    float wv = (L == 0) ? WL[o * FIN + ch * 64 + k] : WL[o * 64 + k];
                    wbuf2[k * 64 + o] = pk2(wv, wv);
                }
            }
            __syncthreads();
            // GEMM: per k: 1 LDS.64 (node pair) + 4 LDS.128 (dup weights) + 8 FFMA2
#pragma unroll 2
            for (int k = 0; k < 64; k++) {
                ull hp = *(const ull*)(ht + k * VSH + pbase);
                const ulonglong2* wp = (const ulonglong2*)(wbuf2 + k * 64 + c8);
                ulonglong2 wa = wp[0], wb = wp[1], wc = wp[2], wd = wp[3];
                fma2(acc[0], hp, wa.x); fma2(acc[1], hp, wa.y);
                fma2(acc[2], hp, wb.x); fma2(acc[3], hp, wb.y);
                fma2(acc[4], hp, wc.x); fma2(acc[5], hp, wc.y);
                fma2(acc[6], hp, wd.x); fma2(acc[7], hp, wd.y);
            }
            __syncthreads();
        }
        // bias + store lin node-major (two STS.128 per node)
        {
            const float* bb = Bp[L];
            float f0[8], f1[8];
#pragma unroll
            for (int t = 0; t < 8; t++) {
                float a, b; upk2(acc[t], a, b);
                float bv = bb[c8 + t];
                f0[t] = a + bv; f1[t] = b + bv;
            }
            float4* r0 = (float4*)(lt + pbase * VSL + c8);
            float4* r1 = (float4*)(lt + (pbase + 1) * VSL + c8);
            r0[0] = make_float4(f0[0], f0[1], f0[2], f0[3]);
            r0[1] = make_float4(f0[4], f0[5], f0[6], f0[7]);
            r1[0] = make_float4(f1[0], f1[1], f1[2], f1[3]);
            r1[1] = make_float4(f1[4], f1[5], f1[6], f1[7]);
        }
        __syncthreads();
        // aggregation: thread = (channel pair c2, node v); per edge: LDS.64 + add2
        {
            const int c2 = 2 * lane;
            const int grp = tid >> 5;            // 0..31
            const float* lc = lt + c2;
            for (int v = grp; v < NPG; v += 32) {
                ull a0 = *(const ull*)(lc + v * VSL);   // self loop
                ull a1 = 0, a2 = 0, a3 = 0;
                int e = roff[v], e1 = roff[v + 1];
                for (; e < e1; e += 8) {
                    uint4 pk = *(const uint4*)(eoff + e);
                    a0 = add2(a0, *(const ull*)(lc + (pk.x & 0xffff)));
                    a1 = add2(a1, *(const ull*)(lc + (pk.x >> 16)));
                    a2 = add2(a2, *(const ull*)(lc + (pk.y & 0xffff)));
                    a3 = add2(a3, *(const ull*)(lc + (pk.y >> 16)));
                    a0 = add2(a0, *(const ull*)(lc + (pk.z & 0xffff)));
                    a1 = add2(a1, *(const ull*)(lc + (pk.z >> 16)));
                    a2 = add2(a2, *(const ull*)(lc + (pk.w & 0xffff)));
                    a3 = add2(a3, *(const ull*)(lc + (pk.w >> 16)));
                }
                ull s = add2(add2(a0, a1), add2(a2, a3));
                float x0, x1; upk2(s, x0, x1);
                float iv = invd[v];
                float t0 = tanhf(x0 * iv);
                float t1 = tanhf(x1 * iv);
                ht[c2 * VSH + v]       = t0;
                ht[(c2 + 1) * VSH + v] = t1;
                *(float2*)(g_feat + (size_t)(g * NPG + v) * FSTR + L * 64 + c2) = make_float2(t0, t1);
            }
        }
        __syncthreads();
    }

    // ---- layer 4: sort scores ----
    if (tid < 64) w4s[tid] = w4[tid];
    __syncthreads();
    if (tid < NPG) {
        float s = b4[0];
#pragma unroll 4
        for (int k = 0; k < 64; k++) s += ht[k * VSH + tid] * w4s[k];
        lt[tid * VSL] = s;
    }
    __syncthreads();
    if (tid < NPG) {
        float a = lt[tid * VSL];
        int e = roff[tid], e1 = roff[tid + 1];
        float a0 = 0.f, a1 = 0.f, a2 = 0.f, a3 = 0.f;
        for (; e < e1; e += 8) {
            uint4 pk = *(const uint4*)(eoff + e);
            a0 += lt[pk.x & 0xffff]; a1 += lt[pk.x >> 16];
            a2 += lt[pk.y & 0xffff]; a3 += lt[pk.y >> 16];
            a0 += lt[pk.z & 0xffff]; a1 += lt[pk.z >> 16];
            a2 += lt[pk.w & 0xffff]; a3 += lt[pk.w >> 16];
        }
        a += (a0 + a1) + (a2 + a3);
        sc[tid] = tanhf(a * invd[tid]);
    }
    __syncthreads();

    // ---- stable top-16: single warp shfl (val desc, idx asc) ----
    if (tid < 32) {
        float v[8];
        const int base = tid * 8;
#pragma unroll
        for (int t = 0; t < 8; t++) v[t] = sc[base + t];
        for (int r = 0; r < KTOP; r++) {
            float bv = v[0]; int bi = base;
#pragma unroll
            for (int t = 1; t < 8; t++)
                if (v[t] > bv) { bv = v[t]; bi = base + t; }
#pragma unroll
            for (int off = 16; off > 0; off >>= 1) {
                float ov = __shfl_xor_sync(0xffffffffu, bv, off);
                int   oi = __shfl_xor_sync(0xffffffffu, bi, off);
                if (ov > bv || (ov == bv && oi < bi)) { bv = ov; bi = oi; }
            }
            if (tid == 0) ord[r] = bi;
            if ((bi >> 3) == tid) v[bi & 7] = -3.4e38f;
        }
    }
    __syncthreads();

    // ---- head (tk in lt, c1ws in ht; both stride 260) ----
    float* tk   = lt;
    float* c1ws = ht;
    for (int i = tid; i < 16 * 257; i += NT) {
        int o = i / 257, d = i - o * 257;
        c1ws[o * 260 + d] = c1w[i];
    }
    for (int i = tid; i < KTOP * 257; i += NT) {
        int l = i / 257, d = i - l * 257;
        tk[l * 260 + d] = (d < 256) ? g_feat[(size_t)(g * NPG + ord[l]) * FSTR + d] : sc[ord[l]];
    }
    __syncthreads();

    if (tid < 256) {
        int o = tid & 15, l = tid >> 4;
        const float4* tr = (const float4*)(tk + l * 260);
        const float4* wr = (const float4*)(c1ws + o * 260);
        float s0 = 0.f, s1 = 0.f, s2 = 0.f, s3 = 0.f;
#pragma unroll 4
        for (int d = 0; d < 64; d++) {
            float4 a = tr[d], b = wr[d];
            s0 += a.x * b.x; s1 += a.y * b.y; s2 += a.z * b.z; s3 += a.w * b.w;
        }
        float s = c1b[o] + tk[l * 260 + 256] * c1ws[o * 260 + 256] + (s0 + s1) + (s2 + s3);
        c1s[o * 16 + l] = fmaxf(s, 0.0f);
    }
    __syncthreads();
    if (tid < 128) {
        int o = tid >> 3, j = tid & 7;
        p1s[tid] = fmaxf(c1s[o * 16 + 2 * j], c1s[o * 16 + 2 * j + 1]);
    }
    __syncthreads();
    if (tid < 128) {
        int oc = tid >> 2, t = tid & 3;
        float s = c2b[oc];
        for (int ic = 0; ic < 16; ic++) {
            const float* pr = &p1s[ic * 8 + t];
            const float* wr = &c2w[oc * 80 + ic * 5];
#pragma unroll
            for (int k = 0; k < 5; k++) s += pr[k] * wr[k];
        }
        flats[tid] = fmaxf(s, 0.0f);
    }
    __syncthreads();
    if (tid < 32) {
        float s = d1b[tid];
        const float4* wr = (const float4*)(d1w + tid * 128);
        const float4* fr = (const float4*)flats;
#pragma unroll 4
        for (int i = 0; i < 32; i++) {
            float4 a = fr[i], b = wr[i];
            s += a.x * b.x + a.y * b.y + a.z * b.z + a.w * b.w;
        }
        float l = fmaxf(s, 0.0f);
        lasts[tid] = l;
        out[2 * NB * TCLS + g * 32 + tid] = l;
    }
    __syncthreads();
    if (tid < TCLS) {
        float s = d2b[tid];
        const float* wr = &d2w[tid * 32];
#pragma unroll
        for (int j = 0; j < 32; j++) s += lasts[j] * wr[j];
        outs[tid] = s;
        out[NB * TCLS + g * TCLS + tid] = s;
    }
    __syncthreads();
    if (tid == 0) {
        float m = outs[0];
        for (int t = 1; t < TCLS; t++) m = fmaxf(m, outs[t]);
        float s = 0.0f;
        for (int t = 0; t < TCLS; t++) s += expf(outs[t] - m);
        lse_s = m + logf(s);
    }
    __syncthreads();
    if (tid < TCLS) out[g * TCLS + tid] = outs[tid] - lse_s;
}

extern "C" void kernel_launch(void* const* d_in, const int* in_sizes, int n_in,
                              void* d_out, int out_size)
{
    const float* x  = (const float*)d_in[0];
    const int*   ei = (const int*)  d_in[1];
    const int wb = (n_in >= 22) ? 4 : 3;
    const float* W[5]; const float* Bv[5];
    for (int i = 0; i < 5; i++) {
        W[i]  = (const float*)d_in[wb + 2 * i];
        Bv[i] = (const float*)d_in[wb + 2 * i + 1];
    }
    const float* c1w = (const float*)d_in[wb + 10];
    const float* c1b = (const float*)d_in[wb + 11];
    const float* c2w = (const float*)d_in[wb + 12];
    const float* c2b = (const float*)d_in[wb + 13];
    const float* d1w = (const float*)d_in[wb + 14];
    const float* d1b = (const float*)d_in[wb + 15];
    const float* d2w = (const float*)d_in[wb + 16];
    const float* d2b = (const float*)d_in[wb + 17];

    cudaFuncSetAttribute(dgcnn_kernel, cudaFuncAttributeMaxDynamicSharedMemorySize, SMEM_BYTES);
    dgcnn_kernel<<<NB, NT, SMEM_BYTES>>>(x, ei,
        W[0], Bv[0], W[1], Bv[1], W[2], Bv[2], W[3], Bv[3], W[4], Bv[4],
        c1w, c1b, c2w, c2b, d1w, d1b, d2w, d2b, (float*)d_out);
}